// round 9
// baseline (speedup 1.0000x reference)
#include <cuda_runtime.h>
#include <cuda_fp16.h>
#include <math_constants.h>
#include <cstdint>

// Problem constants
static constexpr int Bsz = 8192;
static constexpr int S   = 30;
static constexpr int D   = 512;
static constexpr int H   = 1024;
static constexpr int K   = 1536;   // 3*D

static constexpr int NCHUNK = 4;
static constexpr int BCH    = Bsz / NCHUNK;   // 2048 rows per pipeline chunk

// Scratch: fp16 features and fp16 W1 (no device allocs allowed)
__device__ __align__(128) __half g_fh[(size_t)Bsz * K];
__device__ __align__(128) __half g_wh[(size_t)H * K];

// ---------------------------------------------------------------------------
// Helpers
// ---------------------------------------------------------------------------
__device__ __forceinline__ uint32_t smem_u32(const void* p) {
    uint32_t a;
    asm("{ .reg .u64 t; cvta.to.shared.u64 t, %1; cvt.u32.u64 %0, t; }" : "=r"(a) : "l"(p));
    return a;
}

__device__ __forceinline__ void cpa16(uint32_t s, const void* g) {
    asm volatile("cp.async.cg.shared.global [%0], [%1], 16;" :: "r"(s), "l"(g) : "memory");
}

__device__ __forceinline__ void ldsm4(uint32_t* r, uint32_t addr) {
    asm volatile("ldmatrix.sync.aligned.m8n8.x4.shared.b16 {%0,%1,%2,%3}, [%4];"
                 : "=r"(r[0]), "=r"(r[1]), "=r"(r[2]), "=r"(r[3]) : "r"(addr));
}

__device__ __forceinline__ void mma16816(float* d, const uint32_t* a, const uint32_t* b) {
    asm volatile(
        "mma.sync.aligned.m16n8k16.row.col.f32.f16.f16.f32 "
        "{%0,%1,%2,%3}, {%4,%5,%6,%7}, {%8,%9}, {%0,%1,%2,%3};"
        : "+f"(d[0]), "+f"(d[1]), "+f"(d[2]), "+f"(d[3])
        : "r"(a[0]), "r"(a[1]), "r"(a[2]), "r"(a[3]), "r"(b[0]), "r"(b[1]));
}

__device__ __forceinline__ uint32_t sw128(uint32_t off) {
    return off ^ ((off >> 3) & 0x70);
}

// ---------------------------------------------------------------------------
// Kernel 1: feature extraction -> fp16 (per batch chunk)
// ---------------------------------------------------------------------------
__global__ __launch_bounds__(256) void feature_kernel(
    const float* __restrict__ emb,
    const float* __restrict__ wl,
    const float* __restrict__ wm,
    __half* __restrict__ fh)
{
    int t = blockIdx.x * blockDim.x + threadIdx.x;
    int b = t >> 9;
    int d = t & (D - 1);

    const float* p = emb + (size_t)b * (S * D) + d;

    float wl0 = wl[0], wl1 = wl[1], wl2 = wl[2];
    float wm0 = wm[0], wm1 = wm[1], wm2 = wm[2];

    float x0 = p[0];
    float x1 = p[D];
    float vl = -CUDART_INF_F;
    float vm = -CUDART_INF_F;

#pragma unroll
    for (int s = 0; s < 28; ++s) {
        float x2 = p[(s + 2) * D];
        float c = fmaf(x0, wl0, fmaf(x1, wl1, x2 * wl2));
        vl = fmaxf(vl, c);
        if (s >= 23) {
            float cm = fmaf(x0, wm0, fmaf(x1, wm1, x2 * wm2));
            vm = fmaxf(vm, cm);
        }
        x0 = x1;
        x1 = x2;
    }
    float vs = x1;

    size_t base = (size_t)b * K;
    fh[base + d]         = __float2half_rn(vl);
    fh[base + D + d]     = __float2half_rn(vm);
    fh[base + 2 * D + d] = __float2half_rn(vs);
}

// ---------------------------------------------------------------------------
// Kernel 2: W1 -> fp16
// ---------------------------------------------------------------------------
__global__ __launch_bounds__(256) void w1_cvt_kernel(
    const float* __restrict__ W1,
    __half* __restrict__ wh)
{
    int i = blockIdx.x * 256 + threadIdx.x;
    wh[i] = __float2half_rn(W1[i]);
}

// ---------------------------------------------------------------------------
// Kernel 3: mma.sync fp16 GEMM + tanh + W2 reduction (per batch chunk).
//   CTA 128x64, BK=64, 8 warps (4m x 2n), warp tile 32x32, 3-stage cp.async.
//   Small tile -> small T_CTA -> each 256-CTA chunk is one short full wave.
// ---------------------------------------------------------------------------
#define GT 256
#define OFF_A 0
#define OFF_B 16384
#define STAGE 24576
#define NSTAGE 3
#define GEMM_SMEM (NSTAGE * STAGE)   // 72 KB -> 2 CTAs/SM

__device__ __forceinline__ void load_stage(
    uint32_t sbase, const __half* aG, const __half* bG, int k0, int tid)
{
    // A: 128 rows x 8 chunks of 16B = 1024 ops
#pragma unroll
    for (int o = tid; o < 1024; o += GT) {
        int r = o >> 3, c = o & 7;
        uint32_t sw = sw128((uint32_t)(r * 128 + c * 16));
        size_t g = (size_t)r * K + k0 + c * 8;
        cpa16(sbase + OFF_A + sw, aG + g);
    }
    // B: 64 rows x 8 chunks = 512 ops
#pragma unroll
    for (int o = tid; o < 512; o += GT) {
        int r = o >> 3, c = o & 7;
        uint32_t sw = sw128((uint32_t)(r * 128 + c * 16));
        size_t g = (size_t)r * K + k0 + c * 8;
        cpa16(sbase + OFF_B + sw, bG + g);
    }
}

__global__ void __launch_bounds__(GT, 2) gemm_mma_kernel(
    const __half* __restrict__ fh, const __half* __restrict__ wh,
    const float* __restrict__ W2, float* __restrict__ out)
{
    extern __shared__ char smem[];
    const uint32_t sb = smem_u32(smem);
    const int tid  = threadIdx.x;
    const int wid  = tid >> 5;
    const int lane = tid & 31;
    const int wm   = wid & 3;    // m rows wm*32
    const int wn   = wid >> 2;   // n cols wn*32
    const int m0   = blockIdx.x * 128;
    const int n0   = blockIdx.y * 64;

    const __half* aG = fh + (size_t)m0 * K;
    const __half* bG = wh + (size_t)n0 * K;

    float acc[2][4][4];
#pragma unroll
    for (int mt = 0; mt < 2; ++mt)
#pragma unroll
        for (int nt = 0; nt < 4; ++nt)
#pragma unroll
            for (int e = 0; e < 4; ++e) acc[mt][nt][e] = 0.f;

    const int aRow = (lane & 15);
    const int aKch = (lane >> 4);
    const int bRow = ((lane >> 4) << 3) + (lane & 7);
    const int bKch = (lane >> 3) & 1;

    load_stage(sb,             aG, bG, 0,   tid);
    asm volatile("cp.async.commit_group;" ::: "memory");
    load_stage(sb + STAGE,     aG, bG, 64,  tid);
    asm volatile("cp.async.commit_group;" ::: "memory");
    load_stage(sb + 2 * STAGE, aG, bG, 128, tid);
    asm volatile("cp.async.commit_group;" ::: "memory");

    uint32_t sbase = sb;
    for (int c = 0; c < 24; ++c) {
        if (c <= 21)      asm volatile("cp.async.wait_group 2;" ::: "memory");
        else if (c == 22) asm volatile("cp.async.wait_group 1;" ::: "memory");
        else              asm volatile("cp.async.wait_group 0;" ::: "memory");
        __syncthreads();

#pragma unroll
        for (int ks = 0; ks < 4; ++ks) {
            uint32_t ah[2][4], bh[2][4];
#pragma unroll
            for (int mt = 0; mt < 2; ++mt) {
                uint32_t off = (uint32_t)((wm * 32 + mt * 16 + aRow) * 128
                                          + ks * 32 + aKch * 16);
                ldsm4(ah[mt], sbase + OFF_A + sw128(off));
            }
#pragma unroll
            for (int g = 0; g < 2; ++g) {
                uint32_t off = (uint32_t)((wn * 32 + g * 16 + bRow) * 128
                                          + ks * 32 + bKch * 16);
                ldsm4(bh[g], sbase + OFF_B + sw128(off));
            }
#pragma unroll
            for (int mt = 0; mt < 2; ++mt) {
#pragma unroll
                for (int nt = 0; nt < 4; ++nt) {
                    const uint32_t* bp = &bh[nt >> 1][(nt & 1) * 2];
                    mma16816(acc[mt][nt], ah[mt], bp);
                }
            }
        }

        __syncthreads();
        if (c + 3 < 24) {
            load_stage(sbase, aG, bG, (c + 3) * 64, tid);
            asm volatile("cp.async.commit_group;" ::: "memory");
        }
        sbase += STAGE;
        if (sbase == sb + NSTAGE * STAGE) sbase = sb;
    }

    // Epilogue: tanh + W2 dot, quad reduce, atomicAdd per row.
    float w2v[4][2];
#pragma unroll
    for (int nt = 0; nt < 4; ++nt) {
        int col = n0 + wn * 32 + nt * 8 + 2 * (lane & 3);
        w2v[nt][0] = W2[col];
        w2v[nt][1] = W2[col + 1];
    }

#pragma unroll
    for (int mt = 0; mt < 2; ++mt) {
        float p0 = 0.f, p1 = 0.f;
#pragma unroll
        for (int nt = 0; nt < 4; ++nt) {
            p0 += tanhf(acc[mt][nt][0]) * w2v[nt][0]
                + tanhf(acc[mt][nt][1]) * w2v[nt][1];
            p1 += tanhf(acc[mt][nt][2]) * w2v[nt][0]
                + tanhf(acc[mt][nt][3]) * w2v[nt][1];
        }
        p0 += __shfl_xor_sync(0xFFFFFFFFu, p0, 1);
        p0 += __shfl_xor_sync(0xFFFFFFFFu, p0, 2);
        p1 += __shfl_xor_sync(0xFFFFFFFFu, p1, 1);
        p1 += __shfl_xor_sync(0xFFFFFFFFu, p1, 2);
        if ((lane & 3) == 0) {
            int r = m0 + wm * 32 + mt * 16 + (lane >> 2);
            atomicAdd(&out[r], p0);
            atomicAdd(&out[r + 8], p1);
        }
    }
}

// ---------------------------------------------------------------------------
// Launch: fork-join 2-stream pipeline (feature chunks || gemm chunks)
// ---------------------------------------------------------------------------
extern "C" void kernel_launch(void* const* d_in, const int* in_sizes, int n_in,
                              void* d_out, int out_size)
{
    const float* emb    = (const float*)d_in[0];  // [8192, 30, 512]
    const float* w_long = (const float*)d_in[1];  // [3]
    const float* w_mid  = (const float*)d_in[2];  // [3]
    const float* W1     = (const float*)d_in[3];  // [1024, 1536]
    const float* W2     = (const float*)d_in[4];  // [1, 1024]
    float* out = (float*)d_out;                   // [8192]

    __half *fh, *wh;
    cudaGetSymbolAddress((void**)&fh, g_fh);
    cudaGetSymbolAddress((void**)&wh, g_wh);

    // One-time host resources (not device memory; captured work is identical
    // on every call).
    static cudaStream_t s1 = nullptr;
    static cudaEvent_t e_fork, e_join;
    static cudaEvent_t e_feat[NCHUNK];
    if (!s1) {
        cudaStreamCreateWithFlags(&s1, cudaStreamNonBlocking);
        cudaEventCreateWithFlags(&e_fork, cudaEventDisableTiming);
        cudaEventCreateWithFlags(&e_join, cudaEventDisableTiming);
        for (int c = 0; c < NCHUNK; ++c)
            cudaEventCreateWithFlags(&e_feat[c], cudaEventDisableTiming);
    }

    static bool smem_set = false;
    if (!smem_set) {
        cudaFuncSetAttribute(gemm_mma_kernel,
                             cudaFuncAttributeMaxDynamicSharedMemorySize, GEMM_SMEM);
        smem_set = true;
    }

    cudaStream_t s0 = 0;   // capture-origin stream

    cudaMemsetAsync(out, 0, (size_t)Bsz * sizeof(float), s0);
    cudaEventRecord(e_fork, s0);
    cudaStreamWaitEvent(s1, e_fork, 0);

    // s1: W1 conversion (independent of features)
    w1_cvt_kernel<<<(H * K) / 256, 256, 0, s1>>>(W1, wh);

    // s0: feature chunks; s1: gemm chunks gated per-chunk.
    for (int c = 0; c < NCHUNK; ++c) {
        const size_t row0 = (size_t)c * BCH;
        feature_kernel<<<(BCH * D) / 256, 256, 0, s0>>>(
            emb + row0 * (S * D), w_long, w_mid, fh + row0 * K);
        cudaEventRecord(e_feat[c], s0);

        cudaStreamWaitEvent(s1, e_feat[c], 0);
        dim3 grid(BCH / 128, H / 64);   // (16, 16) = 256 CTAs per chunk
        gemm_mma_kernel<<<grid, GT, GEMM_SMEM, s1>>>(
            fh + row0 * K, wh, W2, out + row0);
    }

    cudaEventRecord(e_join, s1);
    cudaStreamWaitEvent(s0, e_join, 0);
}